// round 12
// baseline (speedup 1.0000x reference)
#include <cuda_runtime.h>
#include <cuda_fp16.h>
#include <math.h>
#include <stdint.h>

#define BB 4
#define HH 256
#define WW 256
#define HW 65536

// fp16 channel-last activations
__device__ __half g_inp_t[BB * HW * 128];   // concat input (ch 0..114, pad->128)
__device__ __half g_h_t [BB * HW * 32];     // conv0 out
__device__ __half g_t1_t[BB * HW * 32];     // conv1 out
__device__ __half g_f_t [BB * HW * 32];     // feats fp16 copy (for convf)
// precomputed mma.sync B fragments
__device__ uint2 g_w0f[72 * 128];           // conv0: KS=72, 4 ntiles
__device__ uint2 g_w1f[18 * 128];           // conv1
__device__ uint2 g_w2f[18 * 128];           // conv2
__device__ uint2 g_wff[18 * 32];            // convf: KS=18, 1 ntile (3 valid ch)

__device__ __forceinline__ float lrelu(float v) { return v >= 0.f ? v : 0.1f * v; }

__device__ __forceinline__ unsigned smem_u32(const void* p) {
    return (unsigned)__cvta_generic_to_shared(p);
}
__device__ __forceinline__ void cp_async16(unsigned dst, const void* src, bool p) {
    int sz = p ? 16 : 0;
    asm volatile("cp.async.cg.shared.global [%0], [%1], 16, %2;"
                 :: "r"(dst), "l"(src), "r"(sz));
}
__device__ __forceinline__ void cp_commit() { asm volatile("cp.async.commit_group;"); }
__device__ __forceinline__ void cp_wait0()  { asm volatile("cp.async.wait_group 0;"); }
__device__ __forceinline__ void cp_wait1()  { asm volatile("cp.async.wait_group 1;"); }

#define LDSM_X4(r, addr) \
    asm volatile("ldmatrix.sync.aligned.m8n8.x4.shared.b16 {%0,%1,%2,%3}, [%4];" \
        : "=r"((r)[0]), "=r"((r)[1]), "=r"((r)[2]), "=r"((r)[3]) : "r"(addr))

#define MMA16816(c, a, bf) \
    asm volatile("mma.sync.aligned.m16n8k16.row.col.f32.f16.f16.f32 " \
        "{%0,%1,%2,%3}, {%4,%5,%6,%7}, {%8,%9}, {%0,%1,%2,%3};" \
        : "+f"((c)[0]), "+f"((c)[1]), "+f"((c)[2]), "+f"((c)[3]) \
        : "r"((a)[0]), "r"((a)[1]), "r"((a)[2]), "r"((a)[3]), \
          "r"((bf)[0]), "r"((bf)[1]))

// ===================== correlation + upsample ==============================
// block(32,8): one warp = one 32-pixel row -> conflict-free LDS.
// nb tile staged as float2 channel pairs: LDS.64 + 2 FFMA per 2ch-tap, no cvt.
// Crossbar cost identical to half2 staging; 25% fewer issue slots.
__global__ __launch_bounds__(256) void corr_up_kernel(
    const float* __restrict__ xref, const float* __restrict__ xnb,
    const float* __restrict__ bfeat, const float* __restrict__ bflow,
    __half* __restrict__ inp_t)
{
    const int b  = blockIdx.z;
    const int h0 = blockIdx.y * 8, w0 = blockIdx.x * 32;
    const int tx = threadIdx.x, ty = threadIdx.y;   // (32,8)
    const int tid = ty * 32 + tx;

    __shared__ float2 nb2[4][16][40];   // 4 ch-pairs, 16 halo rows, 40 halo cols

    float acc[81];
#pragma unroll
    for (int k = 0; k < 81; k++) acc[k] = 0.f;
    const int h = h0 + ty, w = w0 + tx;

    for (int c0 = 0; c0 < 32; c0 += 8) {
        // stage 8 channels as 4 float2 pairs over a 16x40 halo tile
        for (int i = tid; i < 4 * 16 * 40; i += 256) {
            int cc2 = i / 640, rem = i % 640;
            int r = rem / 40, cl = rem % 40;
            int gy = h0 - 4 + r, gx = w0 - 4 + cl;
            float2 v = make_float2(0.f, 0.f);
            if (gy >= 0 && gy < HH && gx >= 0 && gx < WW) {
                const float* p = xnb + ((size_t)(b * 32 + c0 + 2 * cc2) * HH + gy) * WW + gx;
                v.x = p[0];
                v.y = p[HW];
            }
            nb2[cc2][r][cl] = v;
        }
        __syncthreads();
#pragma unroll
        for (int cc2 = 0; cc2 < 4; cc2++) {
            const float rlo = xref[((size_t)(b * 32 + c0 + 2 * cc2) * HH + h) * WW + w];
            const float rhi = xref[((size_t)(b * 32 + c0 + 2 * cc2 + 1) * HH + h) * WW + w];
#pragma unroll
            for (int dy = 0; dy < 9; dy++)
#pragma unroll
                for (int dx = 0; dx < 9; dx++) {
                    float2 f = nb2[cc2][ty + dy][tx + dx];
                    acc[dy * 9 + dx] += rlo * f.x + rhi * f.y;
                }
        }
        __syncthreads();
    }

    __half* op = inp_t + ((size_t)(b * HW) + h * WW + w) * 128;
    __half2* op2 = (__half2*)op;
#pragma unroll
    for (int k = 0; k < 40; k++)
        op2[k] = __floats2half2_rn(lrelu(acc[2 * k] * (1.f / 32.f)),
                                   lrelu(acc[2 * k + 1] * (1.f / 32.f)));
    op[80] = __float2half_rn(lrelu(acc[80] * (1.f / 32.f)));

    {
        int iy = h >> 1, ix = w >> 1;
        int ya, yb, xa, xb;
        float wya, wyb, wxa, wxb;
        if ((h & 1) == 0) { ya = max(iy - 1, 0);   yb = iy; wya = 0.25f; wyb = 0.75f; }
        else              { ya = iy; yb = min(iy + 1, 127); wya = 0.75f; wyb = 0.25f; }
        if ((w & 1) == 0) { xa = max(ix - 1, 0);   xb = ix; wxa = 0.25f; wxb = 0.75f; }
        else              { xa = ix; xb = min(ix + 1, 127); wxa = 0.75f; wxb = 0.25f; }

        const float* fp = bfeat + (size_t)b * 32 * 16384;
#pragma unroll 4
        for (int c = 0; c < 32; c++) {
            const float* p = fp + c * 16384;
            float v = wya * (wxa * p[ya * 128 + xa] + wxb * p[ya * 128 + xb])
                    + wyb * (wxa * p[yb * 128 + xa] + wxb * p[yb * 128 + xb]);
            op[81 + c] = __float2half_rn(v);
        }
        const float* lp = bflow + (size_t)b * 2 * 16384;
#pragma unroll
        for (int c = 0; c < 2; c++) {
            const float* p = lp + c * 16384;
            float v = wya * (wxa * p[ya * 128 + xa] + wxb * p[ya * 128 + xb])
                    + wyb * (wxa * p[yb * 128 + xa] + wxb * p[yb * 128 + xb]);
            op[113 + c] = __float2half_rn(v * 2.f);
        }
#pragma unroll
        for (int c = 115; c < 128; c++) op[c] = __float2half_rn(0.f);
    }
}

// ===================== fused B-fragment prep ===============================
template <int CIN, int CS, int NTILES, int NOUT>
__device__ __forceinline__ void fprep_body(
    const float* __restrict__ w, uint2* __restrict__ dst, int idx)
{
    constexpr int KS = (9 * CS) / 16;
    if (idx >= KS * NTILES * 32) return;
    int lane = idx & 31;
    int nt = (idx >> 5) % NTILES;
    int ks = idx / (32 * NTILES);
    int n = nt * 8 + (lane >> 2), q = lane & 3;
    int k0 = ks * 16 + 2 * q;
    float v[4];
#pragma unroll
    for (int u = 0; u < 4; u++) {
        int k = k0 + (u >> 1) * 8 + (u & 1);
        int s = k / (3 * CS), r2 = k % (3 * CS), kx = r2 / CS, c = r2 % CS;
        v[u] = (c < CIN && n < NOUT) ? w[((n * CIN + c) * 3 + s) * 3 + kx] : 0.f;
    }
    __half2 lo = __floats2half2_rn(v[0], v[1]);
    __half2 hi = __floats2half2_rn(v[2], v[3]);
    dst[idx] = make_uint2(*(uint32_t*)&lo, *(uint32_t*)&hi);
}

__global__ __launch_bounds__(256) void fprep_all(
    const float* __restrict__ w0, const float* __restrict__ w1,
    const float* __restrict__ w2, const float* __restrict__ wf,
    uint2* __restrict__ d0, uint2* __restrict__ d1,
    uint2* __restrict__ d2, uint2* __restrict__ df)
{
    int blk = blockIdx.x;
    int t = threadIdx.x;
    if (blk < 36)      fprep_body<115, 128, 4, 32>(w0, d0, blk * 256 + t);
    else if (blk < 45) fprep_body<32, 32, 4, 32>(w1, d1, (blk - 36) * 256 + t);
    else if (blk < 54) fprep_body<32, 32, 4, 32>(w2, d2, (blk - 45) * 256 + t);
    else               fprep_body<32, 32, 1, 3>(wf, df, (blk - 54) * 256 + t);
}

// ===================== conv0 (115->32) via HMMA, DB strips (R10 proven) ====
template <int CS, bool RES>
__global__ __launch_bounds__(256) void conv_hmma_kernel(
    const __half* __restrict__ act_in, const uint2* __restrict__ frags_g,
    const float* __restrict__ bias, const __half* __restrict__ res,
    __half* __restrict__ out16, float* __restrict__ outF32)
{
    constexpr int KSSTRIP = (3 * CS) / 16;
    constexpr int KS      = 3 * KSSTRIP;
    constexpr int ROWH    = CS + 8;
    constexpr int STAGE_HALVES = 2 * 258 * ROWH;
    constexpr int CPP     = CS / 8;

    extern __shared__ __align__(16) unsigned char smem_raw[];
    __half* stage = (__half*)smem_raw;
    uint2*  frags = (uint2*)(smem_raw + STAGE_HALVES * 2);

    const int tid = threadIdx.x;
    const int h = blockIdx.y, b = blockIdx.z;
    const int warp = tid >> 5, lane = tid & 31;
    const int wp0 = warp * 32;
    const int g = lane >> 2, q = lane & 3;

    auto frag_copy = [&]() {
        const uint4* src = (const uint4*)frags_g;
        uint4* dst = (uint4*)frags;
        for (int i = tid; i < (KS * 4 * 32) / 2; i += 256)
            cp_async16(smem_u32(dst + i), src + i, true);
    };
    auto stage_strip = [&](int s, int slot) {
        int gy = h - 1 + s;
        bool rok = (gy >= 0 && gy < HH);
        const __half* rowp = act_in + ((size_t)(b * HW) + (rok ? gy : 0) * WW) * CS;
        for (int i = tid; i < 258 * CPP; i += 256) {
            int ph = i / CPP, cc = i % CPP;
            int gx = ph - 1;
            bool ok = rok && gx >= 0 && gx < WW;
            cp_async16(smem_u32(stage + (slot * 258 + ph) * ROWH + cc * 8),
                       rowp + (ok ? gx : 0) * CS + cc * 8, ok);
        }
    };

    float acc[2][4][4];
#pragma unroll
    for (int mt = 0; mt < 2; mt++)
#pragma unroll
        for (int nt = 0; nt < 4; nt++)
#pragma unroll
            for (int u = 0; u < 4; u++) acc[mt][nt][u] = 0.f;

    auto compute = [&](int s, int slot) {
#pragma unroll 2
        for (int r = 0; r < KSSTRIP; r++) {
            const int kx = r / (CS / 16);
            const int c0 = (r % (CS / 16)) * 16;
            const int ksg = s * KSSTRIP + r;
            uint32_t a[2][4];
#pragma unroll
            for (int mt = 0; mt < 2; mt++) {
                int rowp = wp0 + mt * 16 + (lane & 15) + kx;
                uint32_t addr = smem_u32(
                    stage + (slot * 258 + rowp) * ROWH + c0 + ((lane >> 4) * 8));
                LDSM_X4(a[mt], addr);
            }
#pragma unroll
            for (int nt = 0; nt < 4; nt++) {
                uint2 bfv = frags[(ksg * 4 + nt) * 32 + lane];
                uint32_t bfr[2] = {bfv.x, bfv.y};
                MMA16816(acc[0][nt], a[0], bfr);
                MMA16816(acc[1][nt], a[1], bfr);
            }
        }
    };

    frag_copy(); stage_strip(0, 0); cp_commit();
    stage_strip(1, 1); cp_commit();
    cp_wait1(); __syncthreads();
    compute(0, 0);
    __syncthreads();
    stage_strip(2, 0); cp_commit();
    cp_wait1(); __syncthreads();
    compute(1, 1);
    cp_wait0(); __syncthreads();
    compute(2, 0);

    const size_t rowbase = (size_t)(b * HW) + (size_t)h * WW;
#pragma unroll
    for (int mt = 0; mt < 2; mt++) {
#pragma unroll
        for (int nt = 0; nt < 4; nt++) {
            const int ch = nt * 8 + 2 * q;
            const float bz0 = __ldg(bias + ch), bz1 = __ldg(bias + ch + 1);
#pragma unroll
            for (int rr = 0; rr < 2; rr++) {
                const int p = wp0 + mt * 16 + g + rr * 8;
                float v0 = acc[mt][nt][rr * 2 + 0] + bz0;
                float v1 = acc[mt][nt][rr * 2 + 1] + bz1;
                const size_t pix = rowbase + p;
                if (RES) {
                    __half2 hv = *(const __half2*)(res + pix * 32 + ch);
                    v0 += __low2float(hv);
                    v1 += __high2float(hv);
                }
                v0 = lrelu(v0); v1 = lrelu(v1);
                if (out16)
                    *(__half2*)(out16 + pix * 32 + ch) = __floats2half2_rn(v0, v1);
                if (outF32) {
                    outF32[((size_t)(b * 32 + ch) * HH + h) * WW + p] = v0;
                    outF32[((size_t)(b * 32 + ch + 1) * HH + h) * WW + p] = v1;
                }
            }
        }
    }
}

// ===================== conv 32->32 via HMMA, 2 rows per CTA ================
template <bool RES>
__global__ __launch_bounds__(256) void conv_hmma2_kernel(
    const __half* __restrict__ act_in, const uint2* __restrict__ frags_g,
    const float* __restrict__ bias, const __half* __restrict__ res,
    __half* __restrict__ out16, float* __restrict__ outF32)
{
    constexpr int KSSTRIP = 6, KS = 18, ROWH = 40, CPP = 4;

    extern __shared__ __align__(16) unsigned char smem_raw[];
    __half* stage = (__half*)smem_raw;                    // [4][258][40]
    uint2*  frags = (uint2*)(smem_raw + 4 * 258 * ROWH * 2);

    const int tid = threadIdx.x;
    const int h0 = blockIdx.y * 2, b = blockIdx.z;
    const int warp = tid >> 5, lane = tid & 31;
    const int wp0 = warp * 32;
    const int g = lane >> 2, q = lane & 3;

    {
        const uint4* src = (const uint4*)frags_g;
        uint4* dst = (uint4*)frags;
        for (int i = tid; i < (KS * 4 * 32) / 2; i += 256)
            cp_async16(smem_u32(dst + i), src + i, true);
    }
#pragma unroll
    for (int slot = 0; slot < 4; slot++) {
        int gy = h0 - 1 + slot;
        bool rok = (gy >= 0 && gy < HH);
        const __half* rowp = act_in + ((size_t)(b * HW) + (rok ? gy : 0) * WW) * 32;
        for (int i = tid; i < 258 * CPP; i += 256) {
            int ph = i / CPP, cc = i % CPP;
            int gx = ph - 1;
            bool ok = rok && gx >= 0 && gx < WW;
            cp_async16(smem_u32(stage + (slot * 258 + ph) * ROWH + cc * 8),
                       rowp + (ok ? gx : 0) * 32 + cc * 8, ok);
        }
    }
    cp_commit(); cp_wait0();
    __syncthreads();

    float accA[2][4][4], accB[2][4][4];
#pragma unroll
    for (int mt = 0; mt < 2; mt++)
#pragma unroll
        for (int nt = 0; nt < 4; nt++)
#pragma unroll
            for (int u = 0; u < 4; u++) { accA[mt][nt][u] = 0.f; accB[mt][nt][u] = 0.f; }

#pragma unroll
    for (int slot = 0; slot < 4; slot++) {
#pragma unroll 2
        for (int r = 0; r < KSSTRIP; r++) {
            const int kx = r >> 1;
            const int c0 = (r & 1) * 16;
            uint32_t a[2][4];
#pragma unroll
            for (int mt = 0; mt < 2; mt++) {
                int rowp = wp0 + mt * 16 + (lane & 15) + kx;
                uint32_t addr = smem_u32(
                    stage + (slot * 258 + rowp) * ROWH + c0 + ((lane >> 4) * 8));
                LDSM_X4(a[mt], addr);
            }
            if (slot < 3) {
                const int ksg = slot * KSSTRIP + r;
#pragma unroll
                for (int nt = 0; nt < 4; nt++) {
                    uint2 bfv = frags[(ksg * 4 + nt) * 32 + lane];
                    uint32_t bfr[2] = {bfv.x, bfv.y};
                    MMA16816(accA[0][nt], a[0], bfr);
                    MMA16816(accA[1][nt], a[1], bfr);
                }
            }
            if (slot > 0) {
                const int ksg = (slot - 1) * KSSTRIP + r;
#pragma unroll
                for (int nt = 0; nt < 4; nt++) {
                    uint2 bfv = frags[(ksg * 4 + nt) * 32 + lane];
                    uint32_t bfr[2] = {bfv.x, bfv.y};
                    MMA16816(accB[0][nt], a[0], bfr);
                    MMA16816(accB[1][nt], a[1], bfr);
                }
            }
        }
    }

#pragma unroll
    for (int row = 0; row < 2; row++) {
        const int h = h0 + row;
        const size_t rowbase = (size_t)(b * HW) + (size_t)h * WW;
        float (*acc)[4][4] = row ? accB : accA;
#pragma unroll
        for (int mt = 0; mt < 2; mt++) {
#pragma unroll
            for (int nt = 0; nt < 4; nt++) {
                const int ch = nt * 8 + 2 * q;
                const float bz0 = __ldg(bias + ch), bz1 = __ldg(bias + ch + 1);
#pragma unroll
                for (int rr = 0; rr < 2; rr++) {
                    const int p = wp0 + mt * 16 + g + rr * 8;
                    float v0 = acc[mt][nt][rr * 2 + 0] + bz0;
                    float v1 = acc[mt][nt][rr * 2 + 1] + bz1;
                    const size_t pix = rowbase + p;
                    if (RES) {
                        __half2 hv = *(const __half2*)(res + pix * 32 + ch);
                        v0 += __low2float(hv);
                        v1 += __high2float(hv);
                    }
                    v0 = lrelu(v0); v1 = lrelu(v1);
                    if (out16)
                        *(__half2*)(out16 + pix * 32 + ch) = __floats2half2_rn(v0, v1);
                    if (outF32) {
                        outF32[((size_t)(b * 32 + ch) * HH + h) * WW + p] = v0;
                        outF32[((size_t)(b * 32 + ch + 1) * HH + h) * WW + p] = v1;
                    }
                }
            }
        }
    }
}

// ===================== final conv 32->3 via HMMA, 2 rows per CTA ===========
__global__ __launch_bounds__(256) void convf_hmma2(
    const __half* __restrict__ feats16, const uint2* __restrict__ frags_g,
    const float* __restrict__ bias, float* __restrict__ dout)
{
    constexpr int KSSTRIP = 6, KS = 18, ROWH = 40, CPP = 4;
    extern __shared__ __align__(16) unsigned char smem_raw[];
    __half* stage = (__half*)smem_raw;                    // [4][258][40]
    uint2*  frags = (uint2*)(smem_raw + 4 * 258 * ROWH * 2);

    const int tid = threadIdx.x;
    const int h0 = blockIdx.y * 2, b = blockIdx.z;
    const int warp = tid >> 5, lane = tid & 31;
    const int wp0 = warp * 32;
    const int g = lane >> 2, q = lane & 3;

    {
        const uint4* src = (const uint4*)frags_g;
        uint4* dst = (uint4*)frags;
        for (int i = tid; i < (KS * 32) / 2; i += 256)
            cp_async16(smem_u32(dst + i), src + i, true);
    }
#pragma unroll
    for (int slot = 0; slot < 4; slot++) {
        int gy = h0 - 1 + slot;
        bool rok = (gy >= 0 && gy < HH);
        const __half* rowp = feats16 + ((size_t)(b * HW) + (rok ? gy : 0) * WW) * 32;
        for (int i = tid; i < 258 * CPP; i += 256) {
            int ph = i / CPP, cc = i % CPP;
            int gx = ph - 1;
            bool ok = rok && gx >= 0 && gx < WW;
            cp_async16(smem_u32(stage + (slot * 258 + ph) * ROWH + cc * 8),
                       rowp + (ok ? gx : 0) * 32 + cc * 8, ok);
        }
    }
    cp_commit(); cp_wait0();
    __syncthreads();

    float accA[2][4], accB[2][4];
#pragma unroll
    for (int mt = 0; mt < 2; mt++)
#pragma unroll
        for (int u = 0; u < 4; u++) { accA[mt][u] = 0.f; accB[mt][u] = 0.f; }

#pragma unroll
    for (int slot = 0; slot < 4; slot++) {
#pragma unroll
        for (int r = 0; r < KSSTRIP; r++) {
            const int kx = r >> 1;
            const int c0 = (r & 1) * 16;
            uint32_t a[2][4];
#pragma unroll
            for (int mt = 0; mt < 2; mt++) {
                int rowp = wp0 + mt * 16 + (lane & 15) + kx;
                uint32_t addr = smem_u32(
                    stage + (slot * 258 + rowp) * ROWH + c0 + ((lane >> 4) * 8));
                LDSM_X4(a[mt], addr);
            }
            if (slot < 3) {
                uint2 bfv = frags[(slot * KSSTRIP + r) * 32 + lane];
                uint32_t bfr[2] = {bfv.x, bfv.y};
                MMA16816(accA[0], a[0], bfr);
                MMA16816(accA[1], a[1], bfr);
            }
            if (slot > 0) {
                uint2 bfv = frags[((slot - 1) * KSSTRIP + r) * 32 + lane];
                uint32_t bfr[2] = {bfv.x, bfv.y};
                MMA16816(accB[0], a[0], bfr);
                MMA16816(accB[1], a[1], bfr);
            }
        }
    }

#pragma unroll
    for (int row = 0; row < 2; row++) {
        const int h = h0 + row;
        float (*acc)[4] = row ? accB : accA;
        if (q == 0) {
            const float bz0 = __ldg(bias + 0), bz1 = __ldg(bias + 1);
#pragma unroll
            for (int mt = 0; mt < 2; mt++)
#pragma unroll
                for (int rr = 0; rr < 2; rr++) {
                    const int p = wp0 + mt * 16 + g + rr * 8;
                    const size_t pix = (size_t)h * WW + p;
                    dout[(size_t)(b * 2 + 0) * HW + pix] = acc[mt][rr * 2 + 0] + bz0;
                    dout[(size_t)(b * 2 + 1) * HW + pix] = acc[mt][rr * 2 + 1] + bz1;
                }
        } else if (q == 1) {
            const float bz2 = __ldg(bias + 2);
#pragma unroll
            for (int mt = 0; mt < 2; mt++)
#pragma unroll
                for (int rr = 0; rr < 2; rr++) {
                    const int p = wp0 + mt * 16 + g + rr * 8;
                    const size_t pix = (size_t)h * WW + p;
                    float m = acc[mt][rr * 2 + 0] + bz2;
                    dout[(size_t)(BB * 2) * HW + (size_t)b * HW + pix] =
                        1.f / (1.f + expf(-m));
                }
        }
    }
}

// ===================== launch ==============================================
extern "C" void kernel_launch(void* const* d_in, const int* in_sizes, int n_in,
                              void* d_out, int out_size)
{
    const float* x_ref     = (const float*)d_in[0];
    const float* x_nb      = (const float*)d_in[1];
    const float* base_flow = (const float*)d_in[2];
    const float* base_feat = (const float*)d_in[3];
    const float* w0 = (const float*)d_in[4];
    const float* b0 = (const float*)d_in[5];
    const float* w1 = (const float*)d_in[6];
    const float* b1 = (const float*)d_in[7];
    const float* w2 = (const float*)d_in[8];
    const float* b2 = (const float*)d_in[9];
    const float* wf = (const float*)d_in[10];
    const float* bf = (const float*)d_in[11];

    __half *inp_t, *h_t, *t1_t, *f_t;
    uint2 *w0f, *w1f, *w2f, *wff;
    cudaGetSymbolAddress((void**)&inp_t, g_inp_t);
    cudaGetSymbolAddress((void**)&h_t,  g_h_t);
    cudaGetSymbolAddress((void**)&t1_t, g_t1_t);
    cudaGetSymbolAddress((void**)&f_t,  g_f_t);
    cudaGetSymbolAddress((void**)&w0f, g_w0f);
    cudaGetSymbolAddress((void**)&w1f, g_w1f);
    cudaGetSymbolAddress((void**)&w2f, g_w2f);
    cudaGetSymbolAddress((void**)&wff, g_wff);

    float* out   = (float*)d_out;
    float* feats = out + BB * 2 * HW + BB * HW;

    const int smem0  = (2 * 258 * 136) * 2 + 72 * 4 * 32 * 8;  // 214,080
    const int smem2  = (4 * 258 * 40) * 2 + 18 * 4 * 32 * 8;   // 100,992
    const int smemf2 = (4 * 258 * 40) * 2 + 18 * 32 * 8;       // 87,168
    cudaFuncSetAttribute(conv_hmma_kernel<128, false>,
                         cudaFuncAttributeMaxDynamicSharedMemorySize, smem0);
    cudaFuncSetAttribute(conv_hmma2_kernel<false>,
                         cudaFuncAttributeMaxDynamicSharedMemorySize, smem2);
    cudaFuncSetAttribute(conv_hmma2_kernel<true>,
                         cudaFuncAttributeMaxDynamicSharedMemorySize, smem2);
    cudaFuncSetAttribute(convf_hmma2,
                         cudaFuncAttributeMaxDynamicSharedMemorySize, smemf2);

    dim3 blkC(32, 8);
    dim3 grdCorr(WW / 32, HH / 8, BB);
    dim3 grdH(1, HH, BB);
    dim3 grdH2(1, HH / 2, BB);

    corr_up_kernel<<<grdCorr, blkC>>>(x_ref, x_nb, base_feat, base_flow, inp_t);
    fprep_all<<<57, 256>>>(w0, w1, w2, wf, w0f, w1f, w2f, wff);
    conv_hmma_kernel<128, false><<<grdH, 256, smem0>>>(inp_t, w0f, b0, nullptr, h_t, nullptr);
    conv_hmma2_kernel<false><<<grdH2, 256, smem2>>>(h_t, w1f, b1, nullptr, t1_t, nullptr);
    conv_hmma2_kernel<true ><<<grdH2, 256, smem2>>>(t1_t, w2f, b2, h_t, f_t, feats);
    convf_hmma2<<<grdH2, 256, smemf2>>>(f_t, wff, bf, out);
}

// round 13
// speedup vs baseline: 1.2354x; 1.2354x over previous
#include <cuda_runtime.h>
#include <cuda_fp16.h>
#include <math.h>
#include <stdint.h>

#define BB 4
#define HH 256
#define WW 256
#define HW 65536

// fp16 channel-last activations
__device__ __half g_inp_t[BB * HW * 128];   // concat input (ch 0..114, pad->128)
__device__ __half g_h_t [BB * HW * 32];     // conv0 out
__device__ __half g_t1_t[BB * HW * 32];     // conv1 out
__device__ __half g_f_t [BB * HW * 32];     // feats fp16 copy (for convf)
// precomputed mma.sync B fragments
__device__ uint2 g_w0f[72 * 128];           // conv0: KS=72, 4 ntiles
__device__ uint2 g_w1f[18 * 128];           // conv1
__device__ uint2 g_w2f[18 * 128];           // conv2
__device__ uint2 g_wff[18 * 32];            // convf: KS=18, 1 ntile (3 valid ch)

__device__ __forceinline__ float lrelu(float v) { return v >= 0.f ? v : 0.1f * v; }

__device__ __forceinline__ unsigned smem_u32(const void* p) {
    return (unsigned)__cvta_generic_to_shared(p);
}
__device__ __forceinline__ void cp_async16(unsigned dst, const void* src, bool p) {
    int sz = p ? 16 : 0;
    asm volatile("cp.async.cg.shared.global [%0], [%1], 16, %2;"
                 :: "r"(dst), "l"(src), "r"(sz));
}
__device__ __forceinline__ void cp_commit() { asm volatile("cp.async.commit_group;"); }
__device__ __forceinline__ void cp_wait0()  { asm volatile("cp.async.wait_group 0;"); }
__device__ __forceinline__ void cp_wait1()  { asm volatile("cp.async.wait_group 1;"); }

#define LDSM_X4(r, addr) \
    asm volatile("ldmatrix.sync.aligned.m8n8.x4.shared.b16 {%0,%1,%2,%3}, [%4];" \
        : "=r"((r)[0]), "=r"((r)[1]), "=r"((r)[2]), "=r"((r)[3]) : "r"(addr))

#define MMA16816(c, a, bf) \
    asm volatile("mma.sync.aligned.m16n8k16.row.col.f32.f16.f16.f32 " \
        "{%0,%1,%2,%3}, {%4,%5,%6,%7}, {%8,%9}, {%0,%1,%2,%3};" \
        : "+f"((c)[0]), "+f"((c)[1]), "+f"((c)[2]), "+f"((c)[3]) \
        : "r"((a)[0]), "r"((a)[1]), "r"((a)[2]), "r"((a)[3]), \
          "r"((bf)[0]), "r"((bf)[1]))

// ===================== correlation + upsample (half2 nb tile — proven) =====
// block(32,8): one warp = one 32-pixel row -> conflict-free scalar-stride LDS.
__global__ __launch_bounds__(256) void corr_up_kernel(
    const float* __restrict__ xref, const float* __restrict__ xnb,
    const float* __restrict__ bfeat, const float* __restrict__ bflow,
    __half* __restrict__ inp_t)
{
    const int b  = blockIdx.z;
    const int h0 = blockIdx.y * 8, w0 = blockIdx.x * 32;
    const int tx = threadIdx.x, ty = threadIdx.y;   // (32,8)
    const int tid = ty * 32 + tx;

    __shared__ __half2 nb2[4][16][40];   // 4 ch-pairs, 16 halo rows, 40 halo cols

    float acc[81];
#pragma unroll
    for (int k = 0; k < 81; k++) acc[k] = 0.f;
    const int h = h0 + ty, w = w0 + tx;

    for (int c0 = 0; c0 < 32; c0 += 8) {
        for (int i = tid; i < 4 * 16 * 40; i += 256) {
            int cc2 = i / 640, rem = i % 640;
            int r = rem / 40, cl = rem % 40;
            int gy = h0 - 4 + r, gx = w0 - 4 + cl;
            float v0 = 0.f, v1 = 0.f;
            if (gy >= 0 && gy < HH && gx >= 0 && gx < WW) {
                const float* p = xnb + ((size_t)(b * 32 + c0 + 2 * cc2) * HH + gy) * WW + gx;
                v0 = p[0];
                v1 = p[HW];
            }
            nb2[cc2][r][cl] = __floats2half2_rn(v0, v1);
        }
        __syncthreads();
#pragma unroll
        for (int cc2 = 0; cc2 < 4; cc2++) {
            const float rlo = xref[((size_t)(b * 32 + c0 + 2 * cc2) * HH + h) * WW + w];
            const float rhi = xref[((size_t)(b * 32 + c0 + 2 * cc2 + 1) * HH + h) * WW + w];
#pragma unroll
            for (int dy = 0; dy < 9; dy++)
#pragma unroll
                for (int dx = 0; dx < 9; dx++) {
                    float2 f = __half22float2(nb2[cc2][ty + dy][tx + dx]);
                    acc[dy * 9 + dx] += rlo * f.x + rhi * f.y;
                }
        }
        __syncthreads();
    }

    __half* op = inp_t + ((size_t)(b * HW) + h * WW + w) * 128;
    __half2* op2 = (__half2*)op;
#pragma unroll
    for (int k = 0; k < 40; k++)
        op2[k] = __floats2half2_rn(lrelu(acc[2 * k] * (1.f / 32.f)),
                                   lrelu(acc[2 * k + 1] * (1.f / 32.f)));
    op[80] = __float2half_rn(lrelu(acc[80] * (1.f / 32.f)));

    {
        int iy = h >> 1, ix = w >> 1;
        int ya, yb, xa, xb;
        float wya, wyb, wxa, wxb;
        if ((h & 1) == 0) { ya = max(iy - 1, 0);   yb = iy; wya = 0.25f; wyb = 0.75f; }
        else              { ya = iy; yb = min(iy + 1, 127); wya = 0.75f; wyb = 0.25f; }
        if ((w & 1) == 0) { xa = max(ix - 1, 0);   xb = ix; wxa = 0.25f; wxb = 0.75f; }
        else              { xa = ix; xb = min(ix + 1, 127); wxa = 0.75f; wxb = 0.25f; }

        const float* fp = bfeat + (size_t)b * 32 * 16384;
#pragma unroll 4
        for (int c = 0; c < 32; c++) {
            const float* p = fp + c * 16384;
            float v = wya * (wxa * p[ya * 128 + xa] + wxb * p[ya * 128 + xb])
                    + wyb * (wxa * p[yb * 128 + xa] + wxb * p[yb * 128 + xb]);
            op[81 + c] = __float2half_rn(v);
        }
        const float* lp = bflow + (size_t)b * 2 * 16384;
#pragma unroll
        for (int c = 0; c < 2; c++) {
            const float* p = lp + c * 16384;
            float v = wya * (wxa * p[ya * 128 + xa] + wxb * p[ya * 128 + xb])
                    + wyb * (wxa * p[yb * 128 + xa] + wxb * p[yb * 128 + xb]);
            op[113 + c] = __float2half_rn(v * 2.f);
        }
#pragma unroll
        for (int c = 115; c < 128; c++) op[c] = __float2half_rn(0.f);
    }
}

// ===================== fused B-fragment prep ===============================
template <int CIN, int CS, int NTILES, int NOUT>
__device__ __forceinline__ void fprep_body(
    const float* __restrict__ w, uint2* __restrict__ dst, int idx)
{
    constexpr int KS = (9 * CS) / 16;
    if (idx >= KS * NTILES * 32) return;
    int lane = idx & 31;
    int nt = (idx >> 5) % NTILES;
    int ks = idx / (32 * NTILES);
    int n = nt * 8 + (lane >> 2), q = lane & 3;
    int k0 = ks * 16 + 2 * q;
    float v[4];
#pragma unroll
    for (int u = 0; u < 4; u++) {
        int k = k0 + (u >> 1) * 8 + (u & 1);
        int s = k / (3 * CS), r2 = k % (3 * CS), kx = r2 / CS, c = r2 % CS;
        v[u] = (c < CIN && n < NOUT) ? w[((n * CIN + c) * 3 + s) * 3 + kx] : 0.f;
    }
    __half2 lo = __floats2half2_rn(v[0], v[1]);
    __half2 hi = __floats2half2_rn(v[2], v[3]);
    dst[idx] = make_uint2(*(uint32_t*)&lo, *(uint32_t*)&hi);
}

__global__ __launch_bounds__(256) void fprep_all(
    const float* __restrict__ w0, const float* __restrict__ w1,
    const float* __restrict__ w2, const float* __restrict__ wf,
    uint2* __restrict__ d0, uint2* __restrict__ d1,
    uint2* __restrict__ d2, uint2* __restrict__ df)
{
    int blk = blockIdx.x;
    int t = threadIdx.x;
    if (blk < 36)      fprep_body<115, 128, 4, 32>(w0, d0, blk * 256 + t);
    else if (blk < 45) fprep_body<32, 32, 4, 32>(w1, d1, (blk - 36) * 256 + t);
    else if (blk < 54) fprep_body<32, 32, 4, 32>(w2, d2, (blk - 45) * 256 + t);
    else               fprep_body<32, 32, 1, 3>(wf, df, (blk - 54) * 256 + t);
}

// ===================== conv0 (115->32) via HMMA, DB strips (proven) ========
template <int CS, bool RES>
__global__ __launch_bounds__(256) void conv_hmma_kernel(
    const __half* __restrict__ act_in, const uint2* __restrict__ frags_g,
    const float* __restrict__ bias, const __half* __restrict__ res,
    __half* __restrict__ out16, float* __restrict__ outF32)
{
    constexpr int KSSTRIP = (3 * CS) / 16;
    constexpr int KS      = 3 * KSSTRIP;
    constexpr int ROWH    = CS + 8;
    constexpr int STAGE_HALVES = 2 * 258 * ROWH;
    constexpr int CPP     = CS / 8;

    extern __shared__ __align__(16) unsigned char smem_raw[];
    __half* stage = (__half*)smem_raw;
    uint2*  frags = (uint2*)(smem_raw + STAGE_HALVES * 2);

    const int tid = threadIdx.x;
    const int h = blockIdx.y, b = blockIdx.z;
    const int warp = tid >> 5, lane = tid & 31;
    const int wp0 = warp * 32;
    const int g = lane >> 2, q = lane & 3;

    auto frag_copy = [&]() {
        const uint4* src = (const uint4*)frags_g;
        uint4* dst = (uint4*)frags;
        for (int i = tid; i < (KS * 4 * 32) / 2; i += 256)
            cp_async16(smem_u32(dst + i), src + i, true);
    };
    auto stage_strip = [&](int s, int slot) {
        int gy = h - 1 + s;
        bool rok = (gy >= 0 && gy < HH);
        const __half* rowp = act_in + ((size_t)(b * HW) + (rok ? gy : 0) * WW) * CS;
        for (int i = tid; i < 258 * CPP; i += 256) {
            int ph = i / CPP, cc = i % CPP;
            int gx = ph - 1;
            bool ok = rok && gx >= 0 && gx < WW;
            cp_async16(smem_u32(stage + (slot * 258 + ph) * ROWH + cc * 8),
                       rowp + (ok ? gx : 0) * CS + cc * 8, ok);
        }
    };

    float acc[2][4][4];
#pragma unroll
    for (int mt = 0; mt < 2; mt++)
#pragma unroll
        for (int nt = 0; nt < 4; nt++)
#pragma unroll
            for (int u = 0; u < 4; u++) acc[mt][nt][u] = 0.f;

    auto compute = [&](int s, int slot) {
#pragma unroll 2
        for (int r = 0; r < KSSTRIP; r++) {
            const int kx = r / (CS / 16);
            const int c0 = (r % (CS / 16)) * 16;
            const int ksg = s * KSSTRIP + r;
            uint32_t a[2][4];
#pragma unroll
            for (int mt = 0; mt < 2; mt++) {
                int rowp = wp0 + mt * 16 + (lane & 15) + kx;
                uint32_t addr = smem_u32(
                    stage + (slot * 258 + rowp) * ROWH + c0 + ((lane >> 4) * 8));
                LDSM_X4(a[mt], addr);
            }
#pragma unroll
            for (int nt = 0; nt < 4; nt++) {
                uint2 bfv = frags[(ksg * 4 + nt) * 32 + lane];
                uint32_t bfr[2] = {bfv.x, bfv.y};
                MMA16816(acc[0][nt], a[0], bfr);
                MMA16816(acc[1][nt], a[1], bfr);
            }
        }
    };

    frag_copy(); stage_strip(0, 0); cp_commit();
    stage_strip(1, 1); cp_commit();
    cp_wait1(); __syncthreads();
    compute(0, 0);
    __syncthreads();
    stage_strip(2, 0); cp_commit();
    cp_wait1(); __syncthreads();
    compute(1, 1);
    cp_wait0(); __syncthreads();
    compute(2, 0);

    const size_t rowbase = (size_t)(b * HW) + (size_t)h * WW;
#pragma unroll
    for (int mt = 0; mt < 2; mt++) {
#pragma unroll
        for (int nt = 0; nt < 4; nt++) {
            const int ch = nt * 8 + 2 * q;
            const float bz0 = __ldg(bias + ch), bz1 = __ldg(bias + ch + 1);
#pragma unroll
            for (int rr = 0; rr < 2; rr++) {
                const int p = wp0 + mt * 16 + g + rr * 8;
                float v0 = acc[mt][nt][rr * 2 + 0] + bz0;
                float v1 = acc[mt][nt][rr * 2 + 1] + bz1;
                const size_t pix = rowbase + p;
                if (RES) {
                    __half2 hv = *(const __half2*)(res + pix * 32 + ch);
                    v0 += __low2float(hv);
                    v1 += __high2float(hv);
                }
                v0 = lrelu(v0); v1 = lrelu(v1);
                if (out16)
                    *(__half2*)(out16 + pix * 32 + ch) = __floats2half2_rn(v0, v1);
                if (outF32) {
                    outF32[((size_t)(b * 32 + ch) * HH + h) * WW + p] = v0;
                    outF32[((size_t)(b * 32 + ch + 1) * HH + h) * WW + p] = v1;
                }
            }
        }
    }
}

// ===================== conv 32->32 via HMMA, 2 rows per CTA ================
template <bool RES>
__global__ __launch_bounds__(256) void conv_hmma2_kernel(
    const __half* __restrict__ act_in, const uint2* __restrict__ frags_g,
    const float* __restrict__ bias, const __half* __restrict__ res,
    __half* __restrict__ out16, float* __restrict__ outF32)
{
    constexpr int KSSTRIP = 6, KS = 18, ROWH = 40, CPP = 4;

    extern __shared__ __align__(16) unsigned char smem_raw[];
    __half* stage = (__half*)smem_raw;                    // [4][258][40]
    uint2*  frags = (uint2*)(smem_raw + 4 * 258 * ROWH * 2);

    const int tid = threadIdx.x;
    const int h0 = blockIdx.y * 2, b = blockIdx.z;
    const int warp = tid >> 5, lane = tid & 31;
    const int wp0 = warp * 32;
    const int g = lane >> 2, q = lane & 3;

    {
        const uint4* src = (const uint4*)frags_g;
        uint4* dst = (uint4*)frags;
        for (int i = tid; i < (KS * 4 * 32) / 2; i += 256)
            cp_async16(smem_u32(dst + i), src + i, true);
    }
#pragma unroll
    for (int slot = 0; slot < 4; slot++) {
        int gy = h0 - 1 + slot;
        bool rok = (gy >= 0 && gy < HH);
        const __half* rowp = act_in + ((size_t)(b * HW) + (rok ? gy : 0) * WW) * 32;
        for (int i = tid; i < 258 * CPP; i += 256) {
            int ph = i / CPP, cc = i % CPP;
            int gx = ph - 1;
            bool ok = rok && gx >= 0 && gx < WW;
            cp_async16(smem_u32(stage + (slot * 258 + ph) * ROWH + cc * 8),
                       rowp + (ok ? gx : 0) * 32 + cc * 8, ok);
        }
    }
    cp_commit(); cp_wait0();
    __syncthreads();

    float accA[2][4][4], accB[2][4][4];
#pragma unroll
    for (int mt = 0; mt < 2; mt++)
#pragma unroll
        for (int nt = 0; nt < 4; nt++)
#pragma unroll
            for (int u = 0; u < 4; u++) { accA[mt][nt][u] = 0.f; accB[mt][nt][u] = 0.f; }

#pragma unroll
    for (int slot = 0; slot < 4; slot++) {
#pragma unroll 2
        for (int r = 0; r < KSSTRIP; r++) {
            const int kx = r >> 1;
            const int c0 = (r & 1) * 16;
            uint32_t a[2][4];
#pragma unroll
            for (int mt = 0; mt < 2; mt++) {
                int rowp = wp0 + mt * 16 + (lane & 15) + kx;
                uint32_t addr = smem_u32(
                    stage + (slot * 258 + rowp) * ROWH + c0 + ((lane >> 4) * 8));
                LDSM_X4(a[mt], addr);
            }
            if (slot < 3) {
                const int ksg = slot * KSSTRIP + r;
#pragma unroll
                for (int nt = 0; nt < 4; nt++) {
                    uint2 bfv = frags[(ksg * 4 + nt) * 32 + lane];
                    uint32_t bfr[2] = {bfv.x, bfv.y};
                    MMA16816(accA[0][nt], a[0], bfr);
                    MMA16816(accA[1][nt], a[1], bfr);
                }
            }
            if (slot > 0) {
                const int ksg = (slot - 1) * KSSTRIP + r;
#pragma unroll
                for (int nt = 0; nt < 4; nt++) {
                    uint2 bfv = frags[(ksg * 4 + nt) * 32 + lane];
                    uint32_t bfr[2] = {bfv.x, bfv.y};
                    MMA16816(accB[0][nt], a[0], bfr);
                    MMA16816(accB[1][nt], a[1], bfr);
                }
            }
        }
    }

#pragma unroll
    for (int row = 0; row < 2; row++) {
        const int h = h0 + row;
        const size_t rowbase = (size_t)(b * HW) + (size_t)h * WW;
        float (*acc)[4][4] = row ? accB : accA;
#pragma unroll
        for (int mt = 0; mt < 2; mt++) {
#pragma unroll
            for (int nt = 0; nt < 4; nt++) {
                const int ch = nt * 8 + 2 * q;
                const float bz0 = __ldg(bias + ch), bz1 = __ldg(bias + ch + 1);
#pragma unroll
                for (int rr = 0; rr < 2; rr++) {
                    const int p = wp0 + mt * 16 + g + rr * 8;
                    float v0 = acc[mt][nt][rr * 2 + 0] + bz0;
                    float v1 = acc[mt][nt][rr * 2 + 1] + bz1;
                    const size_t pix = rowbase + p;
                    if (RES) {
                        __half2 hv = *(const __half2*)(res + pix * 32 + ch);
                        v0 += __low2float(hv);
                        v1 += __high2float(hv);
                    }
                    v0 = lrelu(v0); v1 = lrelu(v1);
                    if (out16)
                        *(__half2*)(out16 + pix * 32 + ch) = __floats2half2_rn(v0, v1);
                    if (outF32) {
                        outF32[((size_t)(b * 32 + ch) * HH + h) * WW + p] = v0;
                        outF32[((size_t)(b * 32 + ch + 1) * HH + h) * WW + p] = v1;
                    }
                }
            }
        }
    }
}

// ===================== final conv 32->3 via HMMA, 2 rows per CTA ===========
__global__ __launch_bounds__(256) void convf_hmma2(
    const __half* __restrict__ feats16, const uint2* __restrict__ frags_g,
    const float* __restrict__ bias, float* __restrict__ dout)
{
    constexpr int KSSTRIP = 6, KS = 18, ROWH = 40, CPP = 4;
    extern __shared__ __align__(16) unsigned char smem_raw[];
    __half* stage = (__half*)smem_raw;                    // [4][258][40]
    uint2*  frags = (uint2*)(smem_raw + 4 * 258 * ROWH * 2);

    const int tid = threadIdx.x;
    const int h0 = blockIdx.y * 2, b = blockIdx.z;
    const int warp = tid >> 5, lane = tid & 31;
    const int wp0 = warp * 32;
    const int g = lane >> 2, q = lane & 3;

    {
        const uint4* src = (const uint4*)frags_g;
        uint4* dst = (uint4*)frags;
        for (int i = tid; i < (KS * 32) / 2; i += 256)
            cp_async16(smem_u32(dst + i), src + i, true);
    }
#pragma unroll
    for (int slot = 0; slot < 4; slot++) {
        int gy = h0 - 1 + slot;
        bool rok = (gy >= 0 && gy < HH);
        const __half* rowp = feats16 + ((size_t)(b * HW) + (rok ? gy : 0) * WW) * 32;
        for (int i = tid; i < 258 * CPP; i += 256) {
            int ph = i / CPP, cc = i % CPP;
            int gx = ph - 1;
            bool ok = rok && gx >= 0 && gx < WW;
            cp_async16(smem_u32(stage + (slot * 258 + ph) * ROWH + cc * 8),
                       rowp + (ok ? gx : 0) * 32 + cc * 8, ok);
        }
    }
    cp_commit(); cp_wait0();
    __syncthreads();

    float accA[2][4], accB[2][4];
#pragma unroll
    for (int mt = 0; mt < 2; mt++)
#pragma unroll
        for (int u = 0; u < 4; u++) { accA[mt][u] = 0.f; accB[mt][u] = 0.f; }

#pragma unroll
    for (int slot = 0; slot < 4; slot++) {
#pragma unroll
        for (int r = 0; r < KSSTRIP; r++) {
            const int kx = r >> 1;
            const int c0 = (r & 1) * 16;
            uint32_t a[2][4];
#pragma unroll
            for (int mt = 0; mt < 2; mt++) {
                int rowp = wp0 + mt * 16 + (lane & 15) + kx;
                uint32_t addr = smem_u32(
                    stage + (slot * 258 + rowp) * ROWH + c0 + ((lane >> 4) * 8));
                LDSM_X4(a[mt], addr);
            }
            if (slot < 3) {
                uint2 bfv = frags[(slot * KSSTRIP + r) * 32 + lane];
                uint32_t bfr[2] = {bfv.x, bfv.y};
                MMA16816(accA[0], a[0], bfr);
                MMA16816(accA[1], a[1], bfr);
            }
            if (slot > 0) {
                uint2 bfv = frags[((slot - 1) * KSSTRIP + r) * 32 + lane];
                uint32_t bfr[2] = {bfv.x, bfv.y};
                MMA16816(accB[0], a[0], bfr);
                MMA16816(accB[1], a[1], bfr);
            }
        }
    }

#pragma unroll
    for (int row = 0; row < 2; row++) {
        const int h = h0 + row;
        float (*acc)[4] = row ? accB : accA;
        if (q == 0) {
            const float bz0 = __ldg(bias + 0), bz1 = __ldg(bias + 1);
#pragma unroll
            for (int mt = 0; mt < 2; mt++)
#pragma unroll
                for (int rr = 0; rr < 2; rr++) {
                    const int p = wp0 + mt * 16 + g + rr * 8;
                    const size_t pix = (size_t)h * WW + p;
                    dout[(size_t)(b * 2 + 0) * HW + pix] = acc[mt][rr * 2 + 0] + bz0;
                    dout[(size_t)(b * 2 + 1) * HW + pix] = acc[mt][rr * 2 + 1] + bz1;
                }
        } else if (q == 1) {
            const float bz2 = __ldg(bias + 2);
#pragma unroll
            for (int mt = 0; mt < 2; mt++)
#pragma unroll
                for (int rr = 0; rr < 2; rr++) {
                    const int p = wp0 + mt * 16 + g + rr * 8;
                    const size_t pix = (size_t)h * WW + p;
                    float m = acc[mt][rr * 2 + 0] + bz2;
                    dout[(size_t)(BB * 2) * HW + (size_t)b * HW + pix] =
                        1.f / (1.f + expf(-m));
                }
        }
    }
}

// ===================== launch ==============================================
extern "C" void kernel_launch(void* const* d_in, const int* in_sizes, int n_in,
                              void* d_out, int out_size)
{
    const float* x_ref     = (const float*)d_in[0];
    const float* x_nb      = (const float*)d_in[1];
    const float* base_flow = (const float*)d_in[2];
    const float* base_feat = (const float*)d_in[3];
    const float* w0 = (const float*)d_in[4];
    const float* b0 = (const float*)d_in[5];
    const float* w1 = (const float*)d_in[6];
    const float* b1 = (const float*)d_in[7];
    const float* w2 = (const float*)d_in[8];
    const float* b2 = (const float*)d_in[9];
    const float* wf = (const float*)d_in[10];
    const float* bf = (const float*)d_in[11];

    __half *inp_t, *h_t, *t1_t, *f_t;
    uint2 *w0f, *w1f, *w2f, *wff;
    cudaGetSymbolAddress((void**)&inp_t, g_inp_t);
    cudaGetSymbolAddress((void**)&h_t,  g_h_t);
    cudaGetSymbolAddress((void**)&t1_t, g_t1_t);
    cudaGetSymbolAddress((void**)&f_t,  g_f_t);
    cudaGetSymbolAddress((void**)&w0f, g_w0f);
    cudaGetSymbolAddress((void**)&w1f, g_w1f);
    cudaGetSymbolAddress((void**)&w2f, g_w2f);
    cudaGetSymbolAddress((void**)&wff, g_wff);

    float* out   = (float*)d_out;
    float* feats = out + BB * 2 * HW + BB * HW;

    const int smem0  = (2 * 258 * 136) * 2 + 72 * 4 * 32 * 8;  // 214,080
    const int smem2  = (4 * 258 * 40) * 2 + 18 * 4 * 32 * 8;   // 100,992
    const int smemf2 = (4 * 258 * 40) * 2 + 18 * 32 * 8;       // 87,168
    cudaFuncSetAttribute(conv_hmma_kernel<128, false>,
                         cudaFuncAttributeMaxDynamicSharedMemorySize, smem0);
    cudaFuncSetAttribute(conv_hmma2_kernel<false>,
                         cudaFuncAttributeMaxDynamicSharedMemorySize, smem2);
    cudaFuncSetAttribute(conv_hmma2_kernel<true>,
                         cudaFuncAttributeMaxDynamicSharedMemorySize, smem2);
    cudaFuncSetAttribute(convf_hmma2,
                         cudaFuncAttributeMaxDynamicSharedMemorySize, smemf2);

    dim3 blkC(32, 8);
    dim3 grdCorr(WW / 32, HH / 8, BB);
    dim3 grdH(1, HH, BB);
    dim3 grdH2(1, HH / 2, BB);

    corr_up_kernel<<<grdCorr, blkC>>>(x_ref, x_nb, base_feat, base_flow, inp_t);
    fprep_all<<<57, 256>>>(w0, w1, w2, wf, w0f, w1f, w2f, wff);
    conv_hmma_kernel<128, false><<<grdH, 256, smem0>>>(inp_t, w0f, b0, nullptr, h_t, nullptr);
    conv_hmma2_kernel<false><<<grdH2, 256, smem2>>>(h_t, w1f, b1, nullptr, t1_t, nullptr);
    conv_hmma2_kernel<true ><<<grdH2, 256, smem2>>>(t1_t, w2f, b2, h_t, f_t, feats);
    convf_hmma2<<<grdH2, 256, smemf2>>>(f_t, wff, bf, out);
}

// round 14
// speedup vs baseline: 1.4403x; 1.1659x over previous
#include <cuda_runtime.h>
#include <cuda_fp16.h>
#include <math.h>
#include <stdint.h>

#define BB 4
#define HH 256
#define WW 256
#define HW 65536

// fp16 channel-last activations
__device__ __half g_inp_t[BB * HW * 128];   // concat input (ch 0..114, pad->128)
__device__ __half g_h_t [BB * HW * 32];     // conv0 out
__device__ __half g_t1_t[BB * HW * 32];     // conv1 out
__device__ __half g_f_t [BB * HW * 32];     // feats fp16 copy (for convf)
// precomputed mma.sync B fragments
__device__ uint2 g_w0f[72 * 128];           // conv0: KS=72, 4 ntiles
__device__ uint2 g_w1f[18 * 128];           // conv1
__device__ uint2 g_w2f[18 * 128];           // conv2
__device__ uint2 g_wff[18 * 32];            // convf: KS=18, 1 ntile (3 valid ch)

__device__ __forceinline__ float lrelu(float v) { return v >= 0.f ? v : 0.1f * v; }

__device__ __forceinline__ unsigned smem_u32(const void* p) {
    return (unsigned)__cvta_generic_to_shared(p);
}
__device__ __forceinline__ void cp_async16(unsigned dst, const void* src, bool p) {
    int sz = p ? 16 : 0;
    asm volatile("cp.async.cg.shared.global [%0], [%1], 16, %2;"
                 :: "r"(dst), "l"(src), "r"(sz));
}
__device__ __forceinline__ void cp_commit() { asm volatile("cp.async.commit_group;"); }
__device__ __forceinline__ void cp_wait0()  { asm volatile("cp.async.wait_group 0;"); }
__device__ __forceinline__ void cp_wait1()  { asm volatile("cp.async.wait_group 1;"); }

#define LDSM_X4(r, addr) \
    asm volatile("ldmatrix.sync.aligned.m8n8.x4.shared.b16 {%0,%1,%2,%3}, [%4];" \
        : "=r"((r)[0]), "=r"((r)[1]), "=r"((r)[2]), "=r"((r)[3]) : "r"(addr))

#define LDSM_X2(r0, r1, addr) \
    asm volatile("ldmatrix.sync.aligned.m8n8.x2.shared.b16 {%0,%1}, [%2];" \
        : "=r"(r0), "=r"(r1) : "r"(addr))

#define MMA16816(c, a, bf) \
    asm volatile("mma.sync.aligned.m16n8k16.row.col.f32.f16.f16.f32 " \
        "{%0,%1,%2,%3}, {%4,%5,%6,%7}, {%8,%9}, {%0,%1,%2,%3};" \
        : "+f"((c)[0]), "+f"((c)[1]), "+f"((c)[2]), "+f"((c)[3]) \
        : "r"((a)[0]), "r"((a)[1]), "r"((a)[2]), "r"((a)[3]), \
          "r"((bf)[0]), "r"((bf)[1]))

// ===================== correlation via HMMA (tiled) + upsample =============
// CTA = 32x8 pixel tile. nb halo [16 rows][40 cols][40 ch-stride] fp16 (51KB).
// ref [256px][40] staged into obuf region, lifted to A-frags, then obuf
// [256px][84] reuses it. Warp w: pixel row w, two m16 tiles (px 0-15, 16-31).
// Per (dy, tile): B-frags from halo row w+dy; band scatter dx = n_local - m.
__global__ __launch_bounds__(256) void corr_up_kernel(
    const float* __restrict__ xref, const float* __restrict__ xnb,
    const float* __restrict__ bfeat, const float* __restrict__ bflow,
    __half* __restrict__ inp_t)
{
    extern __shared__ __align__(16) unsigned char smem_raw[];
    __half* nb   = (__half*)smem_raw;            // [16][40][40] = 25600 halves
    __half* obuf = nb + 16 * 40 * 40;            // [256][84] = 21504 halves
    __half* refs = obuf;                         // alias (dead after A-frags)

    const int b  = blockIdx.z;
    const int h0 = blockIdx.y * 8, w0 = blockIdx.x * 32;
    const int tid  = threadIdx.x;
    const int warp = tid >> 5, lane = tid & 31;
    const int g = lane >> 2, q = lane & 3;

    // ---- stage ref [px][ch] (c-major iteration for coalesced LDG) ----
    for (int i = tid; i < 32 * 256; i += 256) {
        int c = i >> 8, px = i & 255;
        float v = xref[((size_t)(b * 32 + c) * HH + h0 + (px >> 5)) * WW + w0 + (px & 31)];
        refs[px * 40 + c] = __float2half_rn(v);
    }
    // ---- stage nb halo [16][40][ch] (channel-pair planes, coalesced) ----
    for (int i = tid; i < 16 * 16 * 40; i += 256) {
        int cp = i / 640, rem = i % 640;
        int r = rem / 40, cl = rem % 40;
        int gy = h0 - 4 + r, gx = w0 - 4 + cl;
        float v0 = 0.f, v1 = 0.f;
        if (gy >= 0 && gy < HH && gx >= 0 && gx < WW) {
            const float* p = xnb + ((size_t)(b * 32 + 2 * cp) * HH + gy) * WW + gx;
            v0 = p[0];
            v1 = p[HW];
        }
        *(__half2*)&nb[(r * 40 + cl) * 40 + 2 * cp] = __floats2half2_rn(v0, v1);
    }
    __syncthreads();

    // ---- A fragments: 2 m-tiles x 2 k-tiles per warp ----
    uint32_t a[2][2][4];
#pragma unroll
    for (int t = 0; t < 2; t++)
#pragma unroll
        for (int kt = 0; kt < 2; kt++) {
            uint32_t addr = smem_u32(refs +
                (warp * 32 + t * 16 + (lane & 15)) * 40 + kt * 16 + (lane >> 4) * 8);
            LDSM_X4(a[t][kt], addr);
        }
    __syncthreads();   // refs region now dead -> obuf

    for (int dy = 0; dy < 9; dy++) {
        const int r = warp + dy;   // halo row for this warp's pixel row
#pragma unroll
        for (int t = 0; t < 2; t++) {
            uint32_t bf[3][2][2];
#pragma unroll
            for (int nt = 0; nt < 3; nt++)
#pragma unroll
                for (int kt = 0; kt < 2; kt++) {
                    uint32_t addr = smem_u32(nb +
                        (r * 40 + t * 16 + nt * 8 + (lane & 7)) * 40 +
                        kt * 16 + ((lane >> 3) & 1) * 8);
                    LDSM_X2(bf[nt][kt][0], bf[nt][kt][1], addr);
                }
            float acc[3][4];
#pragma unroll
            for (int nt = 0; nt < 3; nt++) {
#pragma unroll
                for (int u = 0; u < 4; u++) acc[nt][u] = 0.f;
                MMA16816(acc[nt], a[t][0], bf[nt][0]);
                MMA16816(acc[nt], a[t][1], bf[nt][1]);
            }
            // band scatter: m = g + 8*(u>>1); n_local = nt*8 + 2q + (u&1)
#pragma unroll
            for (int nt = 0; nt < 3; nt++)
#pragma unroll
                for (int u = 0; u < 4; u++) {
                    int m  = g + 8 * (u >> 1);
                    int dx = nt * 8 + 2 * q + (u & 1) - m;
                    if (dx >= 0 && dx <= 8)
                        obuf[(warp * 32 + t * 16 + m) * 84 + dy * 9 + dx] =
                            __float2half_rn(acc[nt][u]);
                }
        }
    }
    __syncthreads();

    // ---- output: one thread per pixel ----
    {
        const int px = tid;
        const int h = h0 + (px >> 5), w = w0 + (px & 31);
        const __half2* row2 = (const __half2*)(obuf + px * 84);
        __half* op = inp_t + ((size_t)(b * HW) + (size_t)h * WW + w) * 128;
        __half2* op2 = (__half2*)op;
#pragma unroll
        for (int k = 0; k < 40; k++) {
            float2 f = __half22float2(row2[k]);
            op2[k] = __floats2half2_rn(lrelu(f.x * (1.f / 32.f)),
                                       lrelu(f.y * (1.f / 32.f)));
        }
        op[80] = __float2half_rn(lrelu(__half2float((obuf + px * 84)[80]) * (1.f / 32.f)));

        int iy = h >> 1, ix = w >> 1;
        int ya, yb, xa, xb;
        float wya, wyb, wxa, wxb;
        if ((h & 1) == 0) { ya = max(iy - 1, 0);   yb = iy; wya = 0.25f; wyb = 0.75f; }
        else              { ya = iy; yb = min(iy + 1, 127); wya = 0.75f; wyb = 0.25f; }
        if ((w & 1) == 0) { xa = max(ix - 1, 0);   xb = ix; wxa = 0.25f; wxb = 0.75f; }
        else              { xa = ix; xb = min(ix + 1, 127); wxa = 0.75f; wxb = 0.25f; }

        const float* fp = bfeat + (size_t)b * 32 * 16384;
#pragma unroll 4
        for (int c = 0; c < 32; c++) {
            const float* p = fp + c * 16384;
            float v = wya * (wxa * p[ya * 128 + xa] + wxb * p[ya * 128 + xb])
                    + wyb * (wxa * p[yb * 128 + xa] + wxb * p[yb * 128 + xb]);
            op[81 + c] = __float2half_rn(v);
        }
        const float* lp = bflow + (size_t)b * 2 * 16384;
#pragma unroll
        for (int c = 0; c < 2; c++) {
            const float* p = lp + c * 16384;
            float v = wya * (wxa * p[ya * 128 + xa] + wxb * p[ya * 128 + xb])
                    + wyb * (wxa * p[yb * 128 + xa] + wxb * p[yb * 128 + xb]);
            op[113 + c] = __float2half_rn(v * 2.f);
        }
#pragma unroll
        for (int c = 115; c < 128; c++) op[c] = __float2half_rn(0.f);
    }
}

// ===================== fused B-fragment prep ===============================
template <int CIN, int CS, int NTILES, int NOUT>
__device__ __forceinline__ void fprep_body(
    const float* __restrict__ w, uint2* __restrict__ dst, int idx)
{
    constexpr int KS = (9 * CS) / 16;
    if (idx >= KS * NTILES * 32) return;
    int lane = idx & 31;
    int nt = (idx >> 5) % NTILES;
    int ks = idx / (32 * NTILES);
    int n = nt * 8 + (lane >> 2), q = lane & 3;
    int k0 = ks * 16 + 2 * q;
    float v[4];
#pragma unroll
    for (int u = 0; u < 4; u++) {
        int k = k0 + (u >> 1) * 8 + (u & 1);
        int s = k / (3 * CS), r2 = k % (3 * CS), kx = r2 / CS, c = r2 % CS;
        v[u] = (c < CIN && n < NOUT) ? w[((n * CIN + c) * 3 + s) * 3 + kx] : 0.f;
    }
    __half2 lo = __floats2half2_rn(v[0], v[1]);
    __half2 hi = __floats2half2_rn(v[2], v[3]);
    dst[idx] = make_uint2(*(uint32_t*)&lo, *(uint32_t*)&hi);
}

__global__ __launch_bounds__(256) void fprep_all(
    const float* __restrict__ w0, const float* __restrict__ w1,
    const float* __restrict__ w2, const float* __restrict__ wf,
    uint2* __restrict__ d0, uint2* __restrict__ d1,
    uint2* __restrict__ d2, uint2* __restrict__ df)
{
    int blk = blockIdx.x;
    int t = threadIdx.x;
    if (blk < 36)      fprep_body<115, 128, 4, 32>(w0, d0, blk * 256 + t);
    else if (blk < 45) fprep_body<32, 32, 4, 32>(w1, d1, (blk - 36) * 256 + t);
    else if (blk < 54) fprep_body<32, 32, 4, 32>(w2, d2, (blk - 45) * 256 + t);
    else               fprep_body<32, 32, 1, 3>(wf, df, (blk - 54) * 256 + t);
}

// ===================== conv0 (115->32) via HMMA, DB strips (proven) ========
template <int CS, bool RES>
__global__ __launch_bounds__(256) void conv_hmma_kernel(
    const __half* __restrict__ act_in, const uint2* __restrict__ frags_g,
    const float* __restrict__ bias, const __half* __restrict__ res,
    __half* __restrict__ out16, float* __restrict__ outF32)
{
    constexpr int KSSTRIP = (3 * CS) / 16;
    constexpr int KS      = 3 * KSSTRIP;
    constexpr int ROWH    = CS + 8;
    constexpr int STAGE_HALVES = 2 * 258 * ROWH;
    constexpr int CPP     = CS / 8;

    extern __shared__ __align__(16) unsigned char smem_raw[];
    __half* stage = (__half*)smem_raw;
    uint2*  frags = (uint2*)(smem_raw + STAGE_HALVES * 2);

    const int tid = threadIdx.x;
    const int h = blockIdx.y, b = blockIdx.z;
    const int warp = tid >> 5, lane = tid & 31;
    const int wp0 = warp * 32;
    const int g = lane >> 2, q = lane & 3;

    auto frag_copy = [&]() {
        const uint4* src = (const uint4*)frags_g;
        uint4* dst = (uint4*)frags;
        for (int i = tid; i < (KS * 4 * 32) / 2; i += 256)
            cp_async16(smem_u32(dst + i), src + i, true);
    };
    auto stage_strip = [&](int s, int slot) {
        int gy = h - 1 + s;
        bool rok = (gy >= 0 && gy < HH);
        const __half* rowp = act_in + ((size_t)(b * HW) + (rok ? gy : 0) * WW) * CS;
        for (int i = tid; i < 258 * CPP; i += 256) {
            int ph = i / CPP, cc = i % CPP;
            int gx = ph - 1;
            bool ok = rok && gx >= 0 && gx < WW;
            cp_async16(smem_u32(stage + (slot * 258 + ph) * ROWH + cc * 8),
                       rowp + (ok ? gx : 0) * CS + cc * 8, ok);
        }
    };

    float acc[2][4][4];
#pragma unroll
    for (int mt = 0; mt < 2; mt++)
#pragma unroll
        for (int nt = 0; nt < 4; nt++)
#pragma unroll
            for (int u = 0; u < 4; u++) acc[mt][nt][u] = 0.f;

    auto compute = [&](int s, int slot) {
#pragma unroll 2
        for (int r = 0; r < KSSTRIP; r++) {
            const int kx = r / (CS / 16);
            const int c0 = (r % (CS / 16)) * 16;
            const int ksg = s * KSSTRIP + r;
            uint32_t a[2][4];
#pragma unroll
            for (int mt = 0; mt < 2; mt++) {
                int rowp = wp0 + mt * 16 + (lane & 15) + kx;
                uint32_t addr = smem_u32(
                    stage + (slot * 258 + rowp) * ROWH + c0 + ((lane >> 4) * 8));
                LDSM_X4(a[mt], addr);
            }
#pragma unroll
            for (int nt = 0; nt < 4; nt++) {
                uint2 bfv = frags[(ksg * 4 + nt) * 32 + lane];
                uint32_t bfr[2] = {bfv.x, bfv.y};
                MMA16816(acc[0][nt], a[0], bfr);
                MMA16816(acc[1][nt], a[1], bfr);
            }
        }
    };

    frag_copy(); stage_strip(0, 0); cp_commit();
    stage_strip(1, 1); cp_commit();
    cp_wait1(); __syncthreads();
    compute(0, 0);
    __syncthreads();
    stage_strip(2, 0); cp_commit();
    cp_wait1(); __syncthreads();
    compute(1, 1);
    cp_wait0(); __syncthreads();
    compute(2, 0);

    const size_t rowbase = (size_t)(b * HW) + (size_t)h * WW;
#pragma unroll
    for (int mt = 0; mt < 2; mt++) {
#pragma unroll
        for (int nt = 0; nt < 4; nt++) {
            const int ch = nt * 8 + 2 * q;
            const float bz0 = __ldg(bias + ch), bz1 = __ldg(bias + ch + 1);
#pragma unroll
            for (int rr = 0; rr < 2; rr++) {
                const int p = wp0 + mt * 16 + g + rr * 8;
                float v0 = acc[mt][nt][rr * 2 + 0] + bz0;
                float v1 = acc[mt][nt][rr * 2 + 1] + bz1;
                const size_t pix = rowbase + p;
                if (RES) {
                    __half2 hv = *(const __half2*)(res + pix * 32 + ch);
                    v0 += __low2float(hv);
                    v1 += __high2float(hv);
                }
                v0 = lrelu(v0); v1 = lrelu(v1);
                if (out16)
                    *(__half2*)(out16 + pix * 32 + ch) = __floats2half2_rn(v0, v1);
                if (outF32) {
                    outF32[((size_t)(b * 32 + ch) * HH + h) * WW + p] = v0;
                    outF32[((size_t)(b * 32 + ch + 1) * HH + h) * WW + p] = v1;
                }
            }
        }
    }
}

// ===================== conv 32->32 via HMMA, 2 rows per CTA ================
template <bool RES>
__global__ __launch_bounds__(256) void conv_hmma2_kernel(
    const __half* __restrict__ act_in, const uint2* __restrict__ frags_g,
    const float* __restrict__ bias, const __half* __restrict__ res,
    __half* __restrict__ out16, float* __restrict__ outF32)
{
    constexpr int KSSTRIP = 6, KS = 18, ROWH = 40, CPP = 4;

    extern __shared__ __align__(16) unsigned char smem_raw[];
    __half* stage = (__half*)smem_raw;                    // [4][258][40]
    uint2*  frags = (uint2*)(smem_raw + 4 * 258 * ROWH * 2);

    const int tid = threadIdx.x;
    const int h0 = blockIdx.y * 2, b = blockIdx.z;
    const int warp = tid >> 5, lane = tid & 31;
    const int wp0 = warp * 32;
    const int g = lane >> 2, q = lane & 3;

    {
        const uint4* src = (const uint4*)frags_g;
        uint4* dst = (uint4*)frags;
        for (int i = tid; i < (KS * 4 * 32) / 2; i += 256)
            cp_async16(smem_u32(dst + i), src + i, true);
    }
#pragma unroll
    for (int slot = 0; slot < 4; slot++) {
        int gy = h0 - 1 + slot;
        bool rok = (gy >= 0 && gy < HH);
        const __half* rowp = act_in + ((size_t)(b * HW) + (rok ? gy : 0) * WW) * 32;
        for (int i = tid; i < 258 * CPP; i += 256) {
            int ph = i / CPP, cc = i % CPP;
            int gx = ph - 1;
            bool ok = rok && gx >= 0 && gx < WW;
            cp_async16(smem_u32(stage + (slot * 258 + ph) * ROWH + cc * 8),
                       rowp + (ok ? gx : 0) * 32 + cc * 8, ok);
        }
    }
    cp_commit(); cp_wait0();
    __syncthreads();

    float accA[2][4][4], accB[2][4][4];
#pragma unroll
    for (int mt = 0; mt < 2; mt++)
#pragma unroll
        for (int nt = 0; nt < 4; nt++)
#pragma unroll
            for (int u = 0; u < 4; u++) { accA[mt][nt][u] = 0.f; accB[mt][nt][u] = 0.f; }

#pragma unroll
    for (int slot = 0; slot < 4; slot++) {
#pragma unroll 2
        for (int r = 0; r < KSSTRIP; r++) {
            const int kx = r >> 1;
            const int c0 = (r & 1) * 16;
            uint32_t a[2][4];
#pragma unroll
            for (int mt = 0; mt < 2; mt++) {
                int rowp = wp0 + mt * 16 + (lane & 15) + kx;
                uint32_t addr = smem_u32(
                    stage + (slot * 258 + rowp) * ROWH + c0 + ((lane >> 4) * 8));
                LDSM_X4(a[mt], addr);
            }
            if (slot < 3) {
                const int ksg = slot * KSSTRIP + r;
#pragma unroll
                for (int nt = 0; nt < 4; nt++) {
                    uint2 bfv = frags[(ksg * 4 + nt) * 32 + lane];
                    uint32_t bfr[2] = {bfv.x, bfv.y};
                    MMA16816(accA[0][nt], a[0], bfr);
                    MMA16816(accA[1][nt], a[1], bfr);
                }
            }
            if (slot > 0) {
                const int ksg = (slot - 1) * KSSTRIP + r;
#pragma unroll
                for (int nt = 0; nt < 4; nt++) {
                    uint2 bfv = frags[(ksg * 4 + nt) * 32 + lane];
                    uint32_t bfr[2] = {bfv.x, bfv.y};
                    MMA16816(accB[0][nt], a[0], bfr);
                    MMA16816(accB[1][nt], a[1], bfr);
                }
            }
        }
    }

#pragma unroll
    for (int row = 0; row < 2; row++) {
        const int h = h0 + row;
        const size_t rowbase = (size_t)(b * HW) + (size_t)h * WW;
        float (*acc)[4][4] = row ? accB : accA;
#pragma unroll
        for (int mt = 0; mt < 2; mt++) {
#pragma unroll
            for (int nt = 0; nt < 4; nt++) {
                const int ch = nt * 8 + 2 * q;
                const float bz0 = __ldg(bias + ch), bz1 = __ldg(bias + ch + 1);
#pragma unroll
                for (int rr = 0; rr < 2; rr++) {
                    const int p = wp0 + mt * 16 + g + rr * 8;
                    float v0 = acc[mt][nt][rr * 2 + 0] + bz0;
                    float v1 = acc[mt][nt][rr * 2 + 1] + bz1;
                    const size_t pix = rowbase + p;
                    if (RES) {
                        __half2 hv = *(const __half2*)(res + pix * 32 + ch);
                        v0 += __low2float(hv);
                        v1 += __high2float(hv);
                    }
                    v0 = lrelu(v0); v1 = lrelu(v1);
                    if (out16)
                        *(__half2*)(out16 + pix * 32 + ch) = __floats2half2_rn(v0, v1);
                    if (outF32) {
                        outF32[((size_t)(b * 32 + ch) * HH + h) * WW + p] = v0;
                        outF32[((size_t)(b * 32 + ch + 1) * HH + h) * WW + p] = v1;
                    }
                }
            }
        }
    }
}

// ===================== final conv 32->3 via HMMA, 2 rows per CTA ===========
__global__ __launch_bounds__(256) void convf_hmma2(
    const __half* __restrict__ feats16, const uint2* __restrict__ frags_g,
    const float* __restrict__ bias, float* __restrict__ dout)
{
    constexpr int KSSTRIP = 6, KS = 18, ROWH = 40, CPP = 4;
    extern __shared__ __align__(16) unsigned char smem_raw[];
    __half* stage = (__half*)smem_raw;                    // [4][258][40]
    uint2*  frags = (uint2*)(smem_raw + 4 * 258 * ROWH * 2);

    const int tid = threadIdx.x;
    const int h0 = blockIdx.y * 2, b = blockIdx.z;
    const int warp = tid >> 5, lane = tid & 31;
    const int wp0 = warp * 32;
    const int g = lane >> 2, q = lane & 3;

    {
        const uint4* src = (const uint4*)frags_g;
        uint4* dst = (uint4*)frags;
        for (int i = tid; i < (KS * 32) / 2; i += 256)
            cp_async16(smem_u32(dst + i), src + i, true);
    }
#pragma unroll
    for (int slot = 0; slot < 4; slot++) {
        int gy = h0 - 1 + slot;
        bool rok = (gy >= 0 && gy < HH);
        const __half* rowp = feats16 + ((size_t)(b * HW) + (rok ? gy : 0) * WW) * 32;
        for (int i = tid; i < 258 * CPP; i += 256) {
            int ph = i / CPP, cc = i % CPP;
            int gx = ph - 1;
            bool ok = rok && gx >= 0 && gx < WW;
            cp_async16(smem_u32(stage + (slot * 258 + ph) * ROWH + cc * 8),
                       rowp + (ok ? gx : 0) * 32 + cc * 8, ok);
        }
    }
    cp_commit(); cp_wait0();
    __syncthreads();

    float accA[2][4], accB[2][4];
#pragma unroll
    for (int mt = 0; mt < 2; mt++)
#pragma unroll
        for (int u = 0; u < 4; u++) { accA[mt][u] = 0.f; accB[mt][u] = 0.f; }

#pragma unroll
    for (int slot = 0; slot < 4; slot++) {
#pragma unroll
        for (int r = 0; r < KSSTRIP; r++) {
            const int kx = r >> 1;
            const int c0 = (r & 1) * 16;
            uint32_t a[2][4];
#pragma unroll
            for (int mt = 0; mt < 2; mt++) {
                int rowp = wp0 + mt * 16 + (lane & 15) + kx;
                uint32_t addr = smem_u32(
                    stage + (slot * 258 + rowp) * ROWH + c0 + ((lane >> 4) * 8));
                LDSM_X4(a[mt], addr);
            }
            if (slot < 3) {
                uint2 bfv = frags[(slot * KSSTRIP + r) * 32 + lane];
                uint32_t bfr[2] = {bfv.x, bfv.y};
                MMA16816(accA[0], a[0], bfr);
                MMA16816(accA[1], a[1], bfr);
            }
            if (slot > 0) {
                uint2 bfv = frags[((slot - 1) * KSSTRIP + r) * 32 + lane];
                uint32_t bfr[2] = {bfv.x, bfv.y};
                MMA16816(accB[0], a[0], bfr);
                MMA16816(accB[1], a[1], bfr);
            }
        }
    }

#pragma unroll
    for (int row = 0; row < 2; row++) {
        const int h = h0 + row;
        float (*acc)[4] = row ? accB : accA;
        if (q == 0) {
            const float bz0 = __ldg(bias + 0), bz1 = __ldg(bias + 1);
#pragma unroll
            for (int mt = 0; mt < 2; mt++)
#pragma unroll
                for (int rr = 0; rr < 2; rr++) {
                    const int p = wp0 + mt * 16 + g + rr * 8;
                    const size_t pix = (size_t)h * WW + p;
                    dout[(size_t)(b * 2 + 0) * HW + pix] = acc[mt][rr * 2 + 0] + bz0;
                    dout[(size_t)(b * 2 + 1) * HW + pix] = acc[mt][rr * 2 + 1] + bz1;
                }
        } else if (q == 1) {
            const float bz2 = __ldg(bias + 2);
#pragma unroll
            for (int mt = 0; mt < 2; mt++)
#pragma unroll
                for (int rr = 0; rr < 2; rr++) {
                    const int p = wp0 + mt * 16 + g + rr * 8;
                    const size_t pix = (size_t)h * WW + p;
                    float m = acc[mt][rr * 2 + 0] + bz2;
                    dout[(size_t)(BB * 2) * HW + (size_t)b * HW + pix] =
                        1.f / (1.f + expf(-m));
                }
        }
    }
}

// ===================== launch ==============================================
extern "C" void kernel_launch(void* const* d_in, const int* in_sizes, int n_in,
                              void* d_out, int out_size)
{
    const float* x_ref     = (const float*)d_in[0];
    const float* x_nb      = (const float*)d_in[1];
    const float* base_flow = (const float*)d_in[2];
    const float* base_feat = (const float*)d_in[3];
    const float* w0 = (const float*)d_in[4];
    const float* b0 = (const float*)d_in[5];
    const float* w1 = (const float*)d_in[6];
    const float* b1 = (const float*)d_in[7];
    const float* w2 = (const float*)d_in[8];
    const float* b2 = (const float*)d_in[9];
    const float* wf = (const float*)d_in[10];
    const float* bf = (const float*)d_in[11];

    __half *inp_t, *h_t, *t1_t, *f_t;
    uint2 *w0f, *w1f, *w2f, *wff;
    cudaGetSymbolAddress((void**)&inp_t, g_inp_t);
    cudaGetSymbolAddress((void**)&h_t,  g_h_t);
    cudaGetSymbolAddress((void**)&t1_t, g_t1_t);
    cudaGetSymbolAddress((void**)&f_t,  g_f_t);
    cudaGetSymbolAddress((void**)&w0f, g_w0f);
    cudaGetSymbolAddress((void**)&w1f, g_w1f);
    cudaGetSymbolAddress((void**)&w2f, g_w2f);
    cudaGetSymbolAddress((void**)&wff, g_wff);

    float* out   = (float*)d_out;
    float* feats = out + BB * 2 * HW + BB * HW;

    const int smemC  = (16 * 40 * 40 + 256 * 84) * 2;          // 94,208
    const int smem0  = (2 * 258 * 136) * 2 + 72 * 4 * 32 * 8;  // 214,080
    const int smem2  = (4 * 258 * 40) * 2 + 18 * 4 * 32 * 8;   // 100,992
    const int smemf2 = (4 * 258 * 40) * 2 + 18 * 32 * 8;       // 87,168
    cudaFuncSetAttribute(corr_up_kernel,
                         cudaFuncAttributeMaxDynamicSharedMemorySize, smemC);
    cudaFuncSetAttribute(conv_hmma_kernel<128, false>,
                         cudaFuncAttributeMaxDynamicSharedMemorySize, smem0);
    cudaFuncSetAttribute(conv_hmma2_kernel<false>,
                         cudaFuncAttributeMaxDynamicSharedMemorySize, smem2);
    cudaFuncSetAttribute(conv_hmma2_kernel<true>,
                         cudaFuncAttributeMaxDynamicSharedMemorySize, smem2);
    cudaFuncSetAttribute(convf_hmma2,
                         cudaFuncAttributeMaxDynamicSharedMemorySize, smemf2);

    dim3 grdCorr(WW / 32, HH / 8, BB);
    dim3 grdH(1, HH, BB);
    dim3 grdH2(1, HH / 2, BB);

    corr_up_kernel<<<grdCorr, 256, smemC>>>(x_ref, x_nb, base_feat, base_flow, inp_t);
    fprep_all<<<57, 256>>>(w0, w1, w2, wf, w0f, w1f, w2f, wff);
    conv_hmma_kernel<128, false><<<grdH, 256, smem0>>>(inp_t, w0f, b0, nullptr, h_t, nullptr);
    conv_hmma2_kernel<false><<<grdH2, 256, smem2>>>(h_t, w1f, b1, nullptr, t1_t, nullptr);
    conv_hmma2_kernel<true ><<<grdH2, 256, smem2>>>(t1_t, w2f, b2, h_t, f_t, feats);
    convf_hmma2<<<grdH2, 256, smemf2>>>(f_t, wff, bf, out);
}